// round 12
// baseline (speedup 1.0000x reference)
#include <cuda_runtime.h>
#include <cuda_bf16.h>
#include <cstdint>

#define NN 50000
#define NE 800000
#define NG 512
#define HID 128
#define EIN 64
#define NTILES (NE / 128)   // 6250 exactly

typedef unsigned long long ull;

// Scratch (device globals: allocation-free rule)
__device__ float g_bufA[NN * HID];   // aggr / MLP input
__device__ float g_bufB[NN * HID];   // MLP hidden
__device__ float g_bufC[NN * HID];   // layer output
__device__ float g_pool[NG * HID];   // pooled per-graph features

// ---- bf16 split helpers ----------------------------------------------------
__device__ __forceinline__ void split2(float a, float b, uint32_t& h, uint32_t& l) {
    __nv_bfloat16 ha = __float2bfloat16_rn(a), hb = __float2bfloat16_rn(b);
    __nv_bfloat162 hh; hh.x = ha; hh.y = hb;
    h = *(uint32_t*)&hh;
    __nv_bfloat162 ll;
    ll.x = __float2bfloat16_rn(a - __bfloat162float(ha));
    ll.y = __float2bfloat16_rn(b - __bfloat162float(hb));
    l = *(uint32_t*)&ll;
}
__device__ __forceinline__ uint32_t packhi2(float a, float b) {
    __nv_bfloat162 hh = __floats2bfloat162_rn(a, b);
    return *(uint32_t*)&hh;
}

__device__ __forceinline__ void mma_bf16(float& c0, float& c1, float& c2, float& c3,
                                         uint32_t a0, uint32_t a1, uint32_t a2, uint32_t a3,
                                         uint32_t b0, uint32_t b1) {
    asm volatile("mma.sync.aligned.m16n8k16.row.col.f32.bf16.bf16.f32 "
                 "{%0,%1,%2,%3}, {%4,%5,%6,%7}, {%8,%9}, {%0,%1,%2,%3};"
                 : "+f"(c0), "+f"(c1), "+f"(c2), "+f"(c3)
                 : "r"(a0), "r"(a1), "r"(a2), "r"(a3), "r"(b0), "r"(b1));
}

__device__ __forceinline__ void ldsm4(uint32_t& r0, uint32_t& r1, uint32_t& r2, uint32_t& r3,
                                      uint32_t addr) {
    asm volatile("ldmatrix.sync.aligned.m8n8.x4.shared.b16 {%0,%1,%2,%3}, [%4];"
                 : "=r"(r0), "=r"(r1), "=r"(r2), "=r"(r3) : "r"(addr));
}
__device__ __forceinline__ uint32_t smem_u32(const void* p) {
    return (uint32_t)__cvta_generic_to_shared(p);
}

// ---------------------------------------------------------------------------
__global__ void copy_kernel(const float4* __restrict__ s, float4* __restrict__ d, int n) {
    int i = blockIdx.x * blockDim.x + threadIdx.x;
    int stride = gridDim.x * blockDim.x;
    for (; i < n; i += stride) d[i] = s[i];
}

// ---------------------------------------------------------------------------
// Tensor-core edge kernel: aggr[dst] += relu(x[src] + attr @ W + b)
// attr in bf16 (hi only); W split hi/lo (2 MMA terms). 3 CTAs/SM.
#define KS 72
#define MSG_S 132
#define SM_WHI  0
#define SM_WLO  18432
#define SM_AHI  36864
#define SM_BIAS 55296
#define SM_MSG  55808      // 32*132*4 = 16896
#define SM_TOTAL_E 72704

__global__ void __launch_bounds__(256, 3)
edge_mma_kernel(const float* __restrict__ xin,
                const float* __restrict__ eattr,
                const int* __restrict__ ei,
                const float* __restrict__ W,       // [64,128]
                const float* __restrict__ bias,    // [128]
                float* __restrict__ aggr) {
    extern __shared__ char smem[];
    __nv_bfloat16* sWhi = (__nv_bfloat16*)(smem + SM_WHI);
    __nv_bfloat16* sWlo = (__nv_bfloat16*)(smem + SM_WLO);
    __nv_bfloat16* sAhi = (__nv_bfloat16*)(smem + SM_AHI);
    float* sBias = (float*)(smem + SM_BIAS);
    float* sMsg  = (float*)(smem + SM_MSG);

    int tid = threadIdx.x;
    int wid = tid >> 5, lane = tid & 31;
    int g = lane >> 2, q = lane & 3;
    int m0 = wid * 16;

    // Stage W transposed: sW[n*KS + k], hi/lo bf16
    {
        int n = tid >> 1, k0 = (tid & 1) * 32;
        for (int j = 0; j < 32; j++) {
            int k = k0 + j;
            float v = W[k * HID + n];
            __nv_bfloat16 h = __float2bfloat16_rn(v);
            sWhi[n * KS + k] = h;
            sWlo[n * KS + k] = __float2bfloat16_rn(v - __bfloat162float(h));
        }
    }
    if (tid < HID) sBias[tid] = bias[tid];
    __syncthreads();

    // ldmatrix per-lane addresses
    int a_row = m0 + (lane & 7) + ((lane >> 3) & 1) * 8;
    int a_k   = (lane >> 4) * 8;
    uint32_t aHoff = smem_u32(sAhi) + (uint32_t)(a_row * KS + a_k) * 2;
    int b_n = (lane & 7) + ((lane >> 4) & 1) * 8;
    int b_k = ((lane >> 3) & 1) * 8;
    uint32_t bHoff = smem_u32(sWhi) + (uint32_t)(b_n * KS + b_k) * 2;
    uint32_t bLoff = smem_u32(sWlo) + (uint32_t)(b_n * KS + b_k) * 2;

    const int* src = ei;
    const int* dst = ei + NE;
    int srow = tid >> 3;
    int sgrp = tid & 7;

    for (int tile = blockIdx.x; tile < NTILES; tile += gridDim.x) {
        int ebase = tile * 128;
        // stage attr tile: sA[r*KS + k], bf16 hi only
        {
            int r = tid >> 1, k0 = (tid & 1) * 32;
            const float4* ap = (const float4*)(eattr + (size_t)(ebase + r) * EIN + k0);
            #pragma unroll
            for (int j = 0; j < 8; j++) {
                float4 v = ap[j];
                *(uint2*)&sAhi[r * KS + k0 + j * 4] =
                    make_uint2(packhi2(v.x, v.y), packhi2(v.z, v.w));
            }
        }
        __syncthreads();

        float acc[16][4];
        #pragma unroll
        for (int nt = 0; nt < 16; nt++)
            #pragma unroll
            for (int c = 0; c < 4; c++) acc[nt][c] = 0.f;

        #pragma unroll
        for (int kt = 0; kt < 4; kt++) {
            uint32_t aH0, aH1, aH2, aH3;
            ldsm4(aH0, aH1, aH2, aH3, aHoff + kt * 32);
            #pragma unroll
            for (int np = 0; np < 8; np++) {
                uint32_t e0, e1, o0, o1;
                uint32_t bofs = np * (16 * KS * 2) + kt * 32;
                ldsm4(e0, e1, o0, o1, bHoff + bofs);
                int nte = np * 2, nto = np * 2 + 1;
                mma_bf16(acc[nte][0], acc[nte][1], acc[nte][2], acc[nte][3],
                         aH0, aH1, aH2, aH3, e0, e1);
                mma_bf16(acc[nto][0], acc[nto][1], acc[nto][2], acc[nto][3],
                         aH0, aH1, aH2, aH3, o0, o1);
                ldsm4(e0, e1, o0, o1, bLoff + bofs);
                mma_bf16(acc[nte][0], acc[nte][1], acc[nte][2], acc[nte][3],
                         aH0, aH1, aH2, aH3, e0, e1);
                mma_bf16(acc[nto][0], acc[nto][1], acc[nto][2], acc[nto][3],
                         aH0, aH1, aH2, aH3, o0, o1);
            }
        }

        // Epilogue: 4 chunks of 32 rows through sMsg, then float4 gather+RED.128
        #pragma unroll
        for (int c = 0; c < 4; c++) {
            if ((wid >> 1) == c) {
                int h = wid & 1;
                #pragma unroll
                for (int nt = 0; nt < 16; nt++) {
                    int col = nt * 8 + 2 * q;
                    *(float2*)&sMsg[(h * 16 + g) * MSG_S + col] =
                        make_float2(acc[nt][0], acc[nt][1]);
                    *(float2*)&sMsg[(h * 16 + g + 8) * MSG_S + col] =
                        make_float2(acc[nt][2], acc[nt][3]);
                }
            }
            __syncthreads();
            int eid = ebase + c * 32 + srow;
            int sI = src[eid], dI = dst[eid];
            const float* xr = xin + (size_t)sI * HID;
            float* ar = aggr + (size_t)dI * HID;
            #pragma unroll
            for (int j = 0; j < 4; j++) {
                int col = (sgrp + j * 8) * 4;
                float4 mv = *(const float4*)&sMsg[srow * MSG_S + col];
                float4 xv = *(const float4*)(xr + col);
                float4 bb = *(const float4*)(sBias + col);
                float4 m;
                m.x = fmaxf(xv.x + bb.x + mv.x, 0.f);
                m.y = fmaxf(xv.y + bb.y + mv.y, 0.f);
                m.z = fmaxf(xv.z + bb.z + mv.z, 0.f);
                m.w = fmaxf(xv.w + bb.w + mv.w, 0.f);
                atomicAdd((float4*)(ar + col), m);
            }
            __syncthreads();
        }
    }
}

// ---------------------------------------------------------------------------
// Tensor-core node GEMM: C[M,128] = act(A[M,128] @ W[128,128] + bias)
// 128x128 tile, K=128 (2 chunks of 64), 8 warps, ldmatrix frags.
#define GKS 136
#define GM_WHI  0            // 128*136*2 = 34816
#define GM_WLO  34816
#define GM_AHI  69632        // 128*72*2 = 18432
#define GM_ALO  88064
#define GM_BIAS 106496
#define GM_TOTAL 107008

__global__ void __launch_bounds__(256, 2)
gemm_mma_kernel(const float* __restrict__ A,
                const float* __restrict__ W,       // [128,128]
                const float* __restrict__ bias,
                float* __restrict__ C,
                int M, int doRelu) {
    extern __shared__ char smem[];
    __nv_bfloat16* sWhi = (__nv_bfloat16*)(smem + GM_WHI);
    __nv_bfloat16* sWlo = (__nv_bfloat16*)(smem + GM_WLO);
    __nv_bfloat16* sAhi = (__nv_bfloat16*)(smem + GM_AHI);
    __nv_bfloat16* sAlo = (__nv_bfloat16*)(smem + GM_ALO);
    float* sBias = (float*)(smem + GM_BIAS);

    int tid = threadIdx.x;
    int wid = tid >> 5, lane = tid & 31;
    int g = lane >> 2, q = lane & 3;
    int m0 = wid * 16;
    int brow = blockIdx.x * 128;

    // Stage W transposed: sW[n*GKS + k], k=0..127, hi/lo
    {
        int n = tid >> 1, k0 = (tid & 1) * 64;
        for (int j = 0; j < 64; j++) {
            int k = k0 + j;
            float v = W[k * HID + n];
            __nv_bfloat16 h = __float2bfloat16_rn(v);
            sWhi[n * GKS + k] = h;
            sWlo[n * GKS + k] = __float2bfloat16_rn(v - __bfloat162float(h));
        }
    }
    if (tid < HID) sBias[tid] = bias[tid];

    int a_row = m0 + (lane & 7) + ((lane >> 3) & 1) * 8;
    int a_k   = (lane >> 4) * 8;
    uint32_t aHoff = smem_u32(sAhi) + (uint32_t)(a_row * KS + a_k) * 2;
    uint32_t aLoff = smem_u32(sAlo) + (uint32_t)(a_row * KS + a_k) * 2;
    int b_n = (lane & 7) + ((lane >> 4) & 1) * 8;
    int b_k = ((lane >> 3) & 1) * 8;
    uint32_t bHoff = smem_u32(sWhi) + (uint32_t)(b_n * GKS + b_k) * 2;
    uint32_t bLoff = smem_u32(sWlo) + (uint32_t)(b_n * GKS + b_k) * 2;

    float acc[16][4];
    #pragma unroll
    for (int nt = 0; nt < 16; nt++)
        #pragma unroll
        for (int c = 0; c < 4; c++) acc[nt][c] = 0.f;

    for (int chunk = 0; chunk < 2; chunk++) {
        // stage A chunk: rows brow..+127, k = chunk*64..+63, stride KS
        {
            int r = tid >> 1, k0 = (tid & 1) * 32;
            int grow = brow + r;
            float4 z = make_float4(0.f, 0.f, 0.f, 0.f);
            const float4* ap = (const float4*)(A + (size_t)grow * HID + chunk * 64 + k0);
            #pragma unroll
            for (int j = 0; j < 8; j++) {
                float4 v = (grow < M) ? ap[j] : z;
                uint32_t h0, l0, h1, l1;
                split2(v.x, v.y, h0, l0);
                split2(v.z, v.w, h1, l1);
                *(uint2*)&sAhi[r * KS + k0 + j * 4] = make_uint2(h0, h1);
                *(uint2*)&sAlo[r * KS + k0 + j * 4] = make_uint2(l0, l1);
            }
        }
        __syncthreads();

        #pragma unroll
        for (int kt = 0; kt < 4; kt++) {
            uint32_t aH0, aH1, aH2, aH3, aL0, aL1, aL2, aL3;
            ldsm4(aH0, aH1, aH2, aH3, aHoff + kt * 32);
            ldsm4(aL0, aL1, aL2, aL3, aLoff + kt * 32);
            uint32_t kofs = (uint32_t)(chunk * 64 + kt * 16) * 2;
            #pragma unroll
            for (int np = 0; np < 8; np++) {
                uint32_t e0, e1, o0, o1;
                uint32_t bofs = np * (16 * GKS * 2) + kofs;
                ldsm4(e0, e1, o0, o1, bHoff + bofs);
                int nte = np * 2, nto = np * 2 + 1;
                mma_bf16(acc[nte][0], acc[nte][1], acc[nte][2], acc[nte][3],
                         aH0, aH1, aH2, aH3, e0, e1);
                mma_bf16(acc[nto][0], acc[nto][1], acc[nto][2], acc[nto][3],
                         aH0, aH1, aH2, aH3, o0, o1);
                mma_bf16(acc[nte][0], acc[nte][1], acc[nte][2], acc[nte][3],
                         aL0, aL1, aL2, aL3, e0, e1);
                mma_bf16(acc[nto][0], acc[nto][1], acc[nto][2], acc[nto][3],
                         aL0, aL1, aL2, aL3, o0, o1);
                ldsm4(e0, e1, o0, o1, bLoff + bofs);
                mma_bf16(acc[nte][0], acc[nte][1], acc[nte][2], acc[nte][3],
                         aH0, aH1, aH2, aH3, e0, e1);
                mma_bf16(acc[nto][0], acc[nto][1], acc[nto][2], acc[nto][3],
                         aH0, aH1, aH2, aH3, o0, o1);
            }
        }
        __syncthreads();
    }

    // Epilogue: rows brow+m0+g (+8), cols nt*8+2q
    int r0 = brow + m0 + g;
    int r1 = r0 + 8;
    #pragma unroll
    for (int nt = 0; nt < 16; nt++) {
        int col = nt * 8 + 2 * q;
        float2 bb = *(const float2*)(sBias + col);
        if (r0 < M) {
            float ox = acc[nt][0] + bb.x, oy = acc[nt][1] + bb.y;
            if (doRelu) { ox = fmaxf(ox, 0.f); oy = fmaxf(oy, 0.f); }
            *(float2*)&C[(size_t)r0 * HID + col] = make_float2(ox, oy);
        }
        if (r1 < M) {
            float ox = acc[nt][2] + bb.x, oy = acc[nt][3] + bb.y;
            if (doRelu) { ox = fmaxf(ox, 0.f); oy = fmaxf(oy, 0.f); }
            *(float2*)&C[(size_t)r1 * HID + col] = make_float2(ox, oy);
        }
    }
}

// ---------------------------------------------------------------------------
__global__ void pool_kernel(const float* __restrict__ h,
                            const int* __restrict__ batch,
                            float* __restrict__ pool) {
    __shared__ int bounds[2];
    int g = blockIdx.x, t = threadIdx.x;  // 128 threads
    if (t < 2) {
        int target = g + t;
        int lo = 0, hi = NN;
        while (lo < hi) {
            int mid = (lo + hi) >> 1;
            if (batch[mid] < target) lo = mid + 1; else hi = mid;
        }
        bounds[t] = lo;
    }
    __syncthreads();
    int lo = bounds[0], hi = bounds[1];
    float s = 0.f;
    for (int n = lo; n < hi; n++) s += h[(size_t)n * HID + t];
    float cnt = (float)((hi - lo) > 1 ? (hi - lo) : 1);
    pool[g * HID + t] = s / cnt;
}

// ---------------------------------------------------------------------------
__global__ void head_kernel(const float* __restrict__ pool,
                            const float* __restrict__ fcw, const float* __restrict__ fcb,
                            const float* __restrict__ hSw, const float* __restrict__ hSb,
                            const float* __restrict__ hPw, const float* __restrict__ hPb,
                            const float* __restrict__ hNw, const float* __restrict__ hNb,
                            float* __restrict__ out) {
    __shared__ float sg[HID];
    __shared__ float red[3][2];
    int g = blockIdx.x, t = threadIdx.x;  // 64 threads
    sg[t]      = pool[g * HID + t];
    sg[t + 64] = pool[g * HID + t + 64];
    __syncthreads();
    float a = fcb[t];
    #pragma unroll 4
    for (int k = 0; k < HID; k++) a = fmaf(sg[k], fcw[k * 64 + t], a);
    float s = fmaxf(a, 0.f);
    float pS = s * hSw[t], pP = s * hPw[t], pN = s * hNw[t];
    #pragma unroll
    for (int off = 16; off; off >>= 1) {
        pS += __shfl_down_sync(0xffffffffu, pS, off);
        pP += __shfl_down_sync(0xffffffffu, pP, off);
        pN += __shfl_down_sync(0xffffffffu, pN, off);
    }
    int warp = t >> 5, lane = t & 31;
    if (lane == 0) { red[0][warp] = pS; red[1][warp] = pP; red[2][warp] = pN; }
    __syncthreads();
    if (t == 0) {
        out[g]            = red[0][0] + red[0][1] + hSb[0];
        out[NG + g]       = red[1][0] + red[1][1] + hPb[0];
        out[2 * NG + g]   = red[2][0] + red[2][1] + hNb[0];
    }
}

// ---------------------------------------------------------------------------
extern "C" void kernel_launch(void* const* d_in, const int* in_sizes, int n_in,
                              void* d_out, int out_size) {
    const float* x     = (const float*)d_in[0];
    const int*   ei    = (const int*)d_in[1];
    const float* eattr = (const float*)d_in[2];
    const int*   batch = (const int*)d_in[3];
    const float *e1w = (const float*)d_in[4],  *e1b = (const float*)d_in[5];
    const float *n1w1 = (const float*)d_in[6], *n1b1 = (const float*)d_in[7];
    const float *n1w2 = (const float*)d_in[8], *n1b2 = (const float*)d_in[9];
    const float *e2w = (const float*)d_in[10], *e2b = (const float*)d_in[11];
    const float *n2w1 = (const float*)d_in[12], *n2b1 = (const float*)d_in[13];
    const float *n2w2 = (const float*)d_in[14], *n2b2 = (const float*)d_in[15];
    const float *fcw = (const float*)d_in[16], *fcb = (const float*)d_in[17];
    const float *hSw = (const float*)d_in[18], *hSb = (const float*)d_in[19];
    const float *hPw = (const float*)d_in[20], *hPb = (const float*)d_in[21];
    const float *hNw = (const float*)d_in[22], *hNb = (const float*)d_in[23];
    float* out = (float*)d_out;

    void *pA, *pB, *pC, *pP;
    cudaGetSymbolAddress(&pA, g_bufA);
    cudaGetSymbolAddress(&pB, g_bufB);
    cudaGetSymbolAddress(&pC, g_bufC);
    cudaGetSymbolAddress(&pP, g_pool);
    float* A = (float*)pA; float* B = (float*)pB;
    float* C = (float*)pC; float* P = (float*)pP;

    const int n4 = NN * HID / 4;
    cudaFuncSetAttribute(edge_mma_kernel, cudaFuncAttributeMaxDynamicSharedMemorySize, SM_TOTAL_E);
    cudaFuncSetAttribute(gemm_mma_kernel, cudaFuncAttributeMaxDynamicSharedMemorySize, GM_TOTAL);
    const int gemm_blocks = (NN + 127) / 128;   // 391
    const int edge_blocks = 444;                // 3 persistent CTAs / SM

    // ----- Layer 1 -----
    copy_kernel<<<4096, 256>>>((const float4*)x, (float4*)A, n4);
    edge_mma_kernel<<<edge_blocks, 256, SM_TOTAL_E>>>(x, eattr, ei, e1w, e1b, A);
    gemm_mma_kernel<<<gemm_blocks, 256, GM_TOTAL>>>(A, n1w1, n1b1, B, NN, 1);
    gemm_mma_kernel<<<gemm_blocks, 256, GM_TOTAL>>>(B, n1w2, n1b2, C, NN, 1);

    // ----- Layer 2 -----
    copy_kernel<<<4096, 256>>>((const float4*)C, (float4*)A, n4);
    edge_mma_kernel<<<edge_blocks, 256, SM_TOTAL_E>>>(C, eattr, ei, e2w, e2b, A);
    gemm_mma_kernel<<<gemm_blocks, 256, GM_TOTAL>>>(A, n2w1, n2b1, B, NN, 1);
    gemm_mma_kernel<<<gemm_blocks, 256, GM_TOTAL>>>(B, n2w2, n2b2, C, NN, 1);

    // ----- Pool + heads -----
    pool_kernel<<<NG, HID>>>(C, batch, P);
    head_kernel<<<NG, 64>>>(P, fcw, fcb, hSw, hSb, hPw, hPb, hNw, hNb, out);
}

// round 13
// speedup vs baseline: 1.5694x; 1.5694x over previous
#include <cuda_runtime.h>
#include <cuda_bf16.h>
#include <cstdint>

#define NN 50000
#define NE 800000
#define NG 512
#define HID 128
#define EIN 64
#define NTILES (NE / 128)   // 6250 exactly

typedef unsigned long long ull;

// Scratch (device globals: allocation-free rule)
__device__ float g_bufA[NN * HID];   // aggr / MLP input
__device__ float g_bufB[NN * HID];   // MLP hidden
__device__ float g_bufC[NN * HID];   // layer output
__device__ float g_pool[NG * HID];   // pooled per-graph features

// ---- bf16 split helpers ----------------------------------------------------
__device__ __forceinline__ void split2(float a, float b, uint32_t& h, uint32_t& l) {
    __nv_bfloat16 ha = __float2bfloat16_rn(a), hb = __float2bfloat16_rn(b);
    __nv_bfloat162 hh; hh.x = ha; hh.y = hb;
    h = *(uint32_t*)&hh;
    __nv_bfloat162 ll;
    ll.x = __float2bfloat16_rn(a - __bfloat162float(ha));
    ll.y = __float2bfloat16_rn(b - __bfloat162float(hb));
    l = *(uint32_t*)&ll;
}
__device__ __forceinline__ uint32_t packhi2(float a, float b) {
    __nv_bfloat162 hh = __floats2bfloat162_rn(a, b);
    return *(uint32_t*)&hh;
}

__device__ __forceinline__ void mma_bf16(float& c0, float& c1, float& c2, float& c3,
                                         uint32_t a0, uint32_t a1, uint32_t a2, uint32_t a3,
                                         uint32_t b0, uint32_t b1) {
    asm volatile("mma.sync.aligned.m16n8k16.row.col.f32.bf16.bf16.f32 "
                 "{%0,%1,%2,%3}, {%4,%5,%6,%7}, {%8,%9}, {%0,%1,%2,%3};"
                 : "+f"(c0), "+f"(c1), "+f"(c2), "+f"(c3)
                 : "r"(a0), "r"(a1), "r"(a2), "r"(a3), "r"(b0), "r"(b1));
}

__device__ __forceinline__ void ldsm4(uint32_t& r0, uint32_t& r1, uint32_t& r2, uint32_t& r3,
                                      uint32_t addr) {
    asm volatile("ldmatrix.sync.aligned.m8n8.x4.shared.b16 {%0,%1,%2,%3}, [%4];"
                 : "=r"(r0), "=r"(r1), "=r"(r2), "=r"(r3) : "r"(addr));
}
__device__ __forceinline__ uint32_t smem_u32(const void* p) {
    return (uint32_t)__cvta_generic_to_shared(p);
}

// ---------------------------------------------------------------------------
__global__ void copy_kernel(const float4* __restrict__ s, float4* __restrict__ d, int n) {
    int i = blockIdx.x * blockDim.x + threadIdx.x;
    int stride = gridDim.x * blockDim.x;
    for (; i < n; i += stride) d[i] = s[i];
}

// ---------------------------------------------------------------------------
// Tensor-core edge kernel: aggr[dst] += relu(x[src] + attr @ W + b)
// attr in bf16 (hi only); W split hi/lo (2 MMA terms). 2 CTAs/SM, no spills.
#define KS 72
#define MSG_S 132
#define SM_WHI  0
#define SM_WLO  18432
#define SM_AHI  36864
#define SM_BIAS 55296
#define SM_MSG  55808      // 32*132*4 = 16896
#define SM_TOTAL_E 72704

__global__ void __launch_bounds__(256, 2)
edge_mma_kernel(const float* __restrict__ xin,
                const float* __restrict__ eattr,
                const int* __restrict__ ei,
                const float* __restrict__ W,       // [64,128]
                const float* __restrict__ bias,    // [128]
                float* __restrict__ aggr) {
    extern __shared__ char smem[];
    __nv_bfloat16* sWhi = (__nv_bfloat16*)(smem + SM_WHI);
    __nv_bfloat16* sWlo = (__nv_bfloat16*)(smem + SM_WLO);
    __nv_bfloat16* sAhi = (__nv_bfloat16*)(smem + SM_AHI);
    float* sBias = (float*)(smem + SM_BIAS);
    float* sMsg  = (float*)(smem + SM_MSG);

    int tid = threadIdx.x;
    int wid = tid >> 5, lane = tid & 31;
    int g = lane >> 2, q = lane & 3;
    int m0 = wid * 16;

    // Stage W transposed: sW[n*KS + k], hi/lo bf16
    {
        int n = tid >> 1, k0 = (tid & 1) * 32;
        for (int j = 0; j < 32; j++) {
            int k = k0 + j;
            float v = W[k * HID + n];
            __nv_bfloat16 h = __float2bfloat16_rn(v);
            sWhi[n * KS + k] = h;
            sWlo[n * KS + k] = __float2bfloat16_rn(v - __bfloat162float(h));
        }
    }
    if (tid < HID) sBias[tid] = bias[tid];
    __syncthreads();

    // ldmatrix per-lane addresses
    int a_row = m0 + (lane & 7) + ((lane >> 3) & 1) * 8;
    int a_k   = (lane >> 4) * 8;
    uint32_t aHoff = smem_u32(sAhi) + (uint32_t)(a_row * KS + a_k) * 2;
    int b_n = (lane & 7) + ((lane >> 4) & 1) * 8;
    int b_k = ((lane >> 3) & 1) * 8;
    uint32_t bHoff = smem_u32(sWhi) + (uint32_t)(b_n * KS + b_k) * 2;
    uint32_t bLoff = smem_u32(sWlo) + (uint32_t)(b_n * KS + b_k) * 2;

    const int* src = ei;
    const int* dst = ei + NE;
    int srow = tid >> 3;
    int sgrp = tid & 7;

    for (int tile = blockIdx.x; tile < NTILES; tile += gridDim.x) {
        int ebase = tile * 128;
        // stage attr tile: sA[r*KS + k], bf16 hi only
        {
            int r = tid >> 1, k0 = (tid & 1) * 32;
            const float4* ap = (const float4*)(eattr + (size_t)(ebase + r) * EIN + k0);
            #pragma unroll
            for (int j = 0; j < 8; j++) {
                float4 v = ap[j];
                *(uint2*)&sAhi[r * KS + k0 + j * 4] =
                    make_uint2(packhi2(v.x, v.y), packhi2(v.z, v.w));
            }
        }
        __syncthreads();

        float acc[16][4];
        #pragma unroll
        for (int nt = 0; nt < 16; nt++)
            #pragma unroll
            for (int c = 0; c < 4; c++) acc[nt][c] = 0.f;

        #pragma unroll
        for (int kt = 0; kt < 4; kt++) {
            uint32_t aH0, aH1, aH2, aH3;
            ldsm4(aH0, aH1, aH2, aH3, aHoff + kt * 32);
            #pragma unroll
            for (int np = 0; np < 8; np++) {
                uint32_t e0, e1, o0, o1;
                uint32_t bofs = np * (16 * KS * 2) + kt * 32;
                ldsm4(e0, e1, o0, o1, bHoff + bofs);
                int nte = np * 2, nto = np * 2 + 1;
                mma_bf16(acc[nte][0], acc[nte][1], acc[nte][2], acc[nte][3],
                         aH0, aH1, aH2, aH3, e0, e1);
                mma_bf16(acc[nto][0], acc[nto][1], acc[nto][2], acc[nto][3],
                         aH0, aH1, aH2, aH3, o0, o1);
                ldsm4(e0, e1, o0, o1, bLoff + bofs);
                mma_bf16(acc[nte][0], acc[nte][1], acc[nte][2], acc[nte][3],
                         aH0, aH1, aH2, aH3, e0, e1);
                mma_bf16(acc[nto][0], acc[nto][1], acc[nto][2], acc[nto][3],
                         aH0, aH1, aH2, aH3, o0, o1);
            }
        }

        // Epilogue: 4 chunks of 32 rows through sMsg, then float4 gather+RED.128
        #pragma unroll
        for (int c = 0; c < 4; c++) {
            if ((wid >> 1) == c) {
                int h = wid & 1;
                #pragma unroll
                for (int nt = 0; nt < 16; nt++) {
                    int col = nt * 8 + 2 * q;
                    *(float2*)&sMsg[(h * 16 + g) * MSG_S + col] =
                        make_float2(acc[nt][0], acc[nt][1]);
                    *(float2*)&sMsg[(h * 16 + g + 8) * MSG_S + col] =
                        make_float2(acc[nt][2], acc[nt][3]);
                }
            }
            __syncthreads();
            int eid = ebase + c * 32 + srow;
            int sI = src[eid], dI = dst[eid];
            const float* xr = xin + (size_t)sI * HID;
            float* ar = aggr + (size_t)dI * HID;
            #pragma unroll
            for (int j = 0; j < 4; j++) {
                int col = (sgrp + j * 8) * 4;
                float4 mv = *(const float4*)&sMsg[srow * MSG_S + col];
                float4 xv = *(const float4*)(xr + col);
                float4 bb = *(const float4*)(sBias + col);
                float4 m;
                m.x = fmaxf(xv.x + bb.x + mv.x, 0.f);
                m.y = fmaxf(xv.y + bb.y + mv.y, 0.f);
                m.z = fmaxf(xv.z + bb.z + mv.z, 0.f);
                m.w = fmaxf(xv.w + bb.w + mv.w, 0.f);
                atomicAdd((float4*)(ar + col), m);
            }
            __syncthreads();
        }
    }
}

// ---------------------------------------------------------------------------
// Tensor-core node GEMM: C[M,128] = act(A[M,128] @ W[128,128] + bias)
// 128x128 tile, K=128 (2 chunks of 64), 8 warps, ldmatrix frags.
#define GKS 136
#define GM_WHI  0            // 128*136*2 = 34816
#define GM_WLO  34816
#define GM_AHI  69632        // 128*72*2 = 18432
#define GM_ALO  88064
#define GM_BIAS 106496
#define GM_TOTAL 107008

__global__ void __launch_bounds__(256, 2)
gemm_mma_kernel(const float* __restrict__ A,
                const float* __restrict__ W,       // [128,128]
                const float* __restrict__ bias,
                float* __restrict__ C,
                int M, int doRelu) {
    extern __shared__ char smem[];
    __nv_bfloat16* sWhi = (__nv_bfloat16*)(smem + GM_WHI);
    __nv_bfloat16* sWlo = (__nv_bfloat16*)(smem + GM_WLO);
    __nv_bfloat16* sAhi = (__nv_bfloat16*)(smem + GM_AHI);
    __nv_bfloat16* sAlo = (__nv_bfloat16*)(smem + GM_ALO);
    float* sBias = (float*)(smem + GM_BIAS);

    int tid = threadIdx.x;
    int wid = tid >> 5, lane = tid & 31;
    int g = lane >> 2, q = lane & 3;
    int m0 = wid * 16;
    int brow = blockIdx.x * 128;

    // Stage W transposed: sW[n*GKS + k], k=0..127, hi/lo
    {
        int n = tid >> 1, k0 = (tid & 1) * 64;
        for (int j = 0; j < 64; j++) {
            int k = k0 + j;
            float v = W[k * HID + n];
            __nv_bfloat16 h = __float2bfloat16_rn(v);
            sWhi[n * GKS + k] = h;
            sWlo[n * GKS + k] = __float2bfloat16_rn(v - __bfloat162float(h));
        }
    }
    if (tid < HID) sBias[tid] = bias[tid];

    int a_row = m0 + (lane & 7) + ((lane >> 3) & 1) * 8;
    int a_k   = (lane >> 4) * 8;
    uint32_t aHoff = smem_u32(sAhi) + (uint32_t)(a_row * KS + a_k) * 2;
    uint32_t aLoff = smem_u32(sAlo) + (uint32_t)(a_row * KS + a_k) * 2;
    int b_n = (lane & 7) + ((lane >> 4) & 1) * 8;
    int b_k = ((lane >> 3) & 1) * 8;
    uint32_t bHoff = smem_u32(sWhi) + (uint32_t)(b_n * GKS + b_k) * 2;
    uint32_t bLoff = smem_u32(sWlo) + (uint32_t)(b_n * GKS + b_k) * 2;

    float acc[16][4];
    #pragma unroll
    for (int nt = 0; nt < 16; nt++)
        #pragma unroll
        for (int c = 0; c < 4; c++) acc[nt][c] = 0.f;

    for (int chunk = 0; chunk < 2; chunk++) {
        // stage A chunk: rows brow..+127, k = chunk*64..+63, stride KS
        {
            int r = tid >> 1, k0 = (tid & 1) * 32;
            int grow = brow + r;
            float4 z = make_float4(0.f, 0.f, 0.f, 0.f);
            const float4* ap = (const float4*)(A + (size_t)grow * HID + chunk * 64 + k0);
            #pragma unroll
            for (int j = 0; j < 8; j++) {
                float4 v = (grow < M) ? ap[j] : z;
                uint32_t h0, l0, h1, l1;
                split2(v.x, v.y, h0, l0);
                split2(v.z, v.w, h1, l1);
                *(uint2*)&sAhi[r * KS + k0 + j * 4] = make_uint2(h0, h1);
                *(uint2*)&sAlo[r * KS + k0 + j * 4] = make_uint2(l0, l1);
            }
        }
        __syncthreads();

        #pragma unroll
        for (int kt = 0; kt < 4; kt++) {
            uint32_t aH0, aH1, aH2, aH3, aL0, aL1, aL2, aL3;
            ldsm4(aH0, aH1, aH2, aH3, aHoff + kt * 32);
            ldsm4(aL0, aL1, aL2, aL3, aLoff + kt * 32);
            uint32_t kofs = (uint32_t)(chunk * 64 + kt * 16) * 2;
            #pragma unroll
            for (int np = 0; np < 8; np++) {
                uint32_t e0, e1, o0, o1;
                uint32_t bofs = np * (16 * GKS * 2) + kofs;
                ldsm4(e0, e1, o0, o1, bHoff + bofs);
                int nte = np * 2, nto = np * 2 + 1;
                mma_bf16(acc[nte][0], acc[nte][1], acc[nte][2], acc[nte][3],
                         aH0, aH1, aH2, aH3, e0, e1);
                mma_bf16(acc[nto][0], acc[nto][1], acc[nto][2], acc[nto][3],
                         aH0, aH1, aH2, aH3, o0, o1);
                mma_bf16(acc[nte][0], acc[nte][1], acc[nte][2], acc[nte][3],
                         aL0, aL1, aL2, aL3, e0, e1);
                mma_bf16(acc[nto][0], acc[nto][1], acc[nto][2], acc[nto][3],
                         aL0, aL1, aL2, aL3, o0, o1);
                ldsm4(e0, e1, o0, o1, bLoff + bofs);
                mma_bf16(acc[nte][0], acc[nte][1], acc[nte][2], acc[nte][3],
                         aH0, aH1, aH2, aH3, e0, e1);
                mma_bf16(acc[nto][0], acc[nto][1], acc[nto][2], acc[nto][3],
                         aH0, aH1, aH2, aH3, o0, o1);
            }
        }
        __syncthreads();
    }

    // Epilogue: rows brow+m0+g (+8), cols nt*8+2q
    int r0 = brow + m0 + g;
    int r1 = r0 + 8;
    #pragma unroll
    for (int nt = 0; nt < 16; nt++) {
        int col = nt * 8 + 2 * q;
        float2 bb = *(const float2*)(sBias + col);
        if (r0 < M) {
            float ox = acc[nt][0] + bb.x, oy = acc[nt][1] + bb.y;
            if (doRelu) { ox = fmaxf(ox, 0.f); oy = fmaxf(oy, 0.f); }
            *(float2*)&C[(size_t)r0 * HID + col] = make_float2(ox, oy);
        }
        if (r1 < M) {
            float ox = acc[nt][2] + bb.x, oy = acc[nt][3] + bb.y;
            if (doRelu) { ox = fmaxf(ox, 0.f); oy = fmaxf(oy, 0.f); }
            *(float2*)&C[(size_t)r1 * HID + col] = make_float2(ox, oy);
        }
    }
}

// ---------------------------------------------------------------------------
__global__ void pool_kernel(const float* __restrict__ h,
                            const int* __restrict__ batch,
                            float* __restrict__ pool) {
    __shared__ int bounds[2];
    int g = blockIdx.x, t = threadIdx.x;  // 128 threads
    if (t < 2) {
        int target = g + t;
        int lo = 0, hi = NN;
        while (lo < hi) {
            int mid = (lo + hi) >> 1;
            if (batch[mid] < target) lo = mid + 1; else hi = mid;
        }
        bounds[t] = lo;
    }
    __syncthreads();
    int lo = bounds[0], hi = bounds[1];
    float s = 0.f;
    for (int n = lo; n < hi; n++) s += h[(size_t)n * HID + t];
    float cnt = (float)((hi - lo) > 1 ? (hi - lo) : 1);
    pool[g * HID + t] = s / cnt;
}

// ---------------------------------------------------------------------------
__global__ void head_kernel(const float* __restrict__ pool,
                            const float* __restrict__ fcw, const float* __restrict__ fcb,
                            const float* __restrict__ hSw, const float* __restrict__ hSb,
                            const float* __restrict__ hPw, const float* __restrict__ hPb,
                            const float* __restrict__ hNw, const float* __restrict__ hNb,
                            float* __restrict__ out) {
    __shared__ float sg[HID];
    __shared__ float red[3][2];
    int g = blockIdx.x, t = threadIdx.x;  // 64 threads
    sg[t]      = pool[g * HID + t];
    sg[t + 64] = pool[g * HID + t + 64];
    __syncthreads();
    float a = fcb[t];
    #pragma unroll 4
    for (int k = 0; k < HID; k++) a = fmaf(sg[k], fcw[k * 64 + t], a);
    float s = fmaxf(a, 0.f);
    float pS = s * hSw[t], pP = s * hPw[t], pN = s * hNw[t];
    #pragma unroll
    for (int off = 16; off; off >>= 1) {
        pS += __shfl_down_sync(0xffffffffu, pS, off);
        pP += __shfl_down_sync(0xffffffffu, pP, off);
        pN += __shfl_down_sync(0xffffffffu, pN, off);
    }
    int warp = t >> 5, lane = t & 31;
    if (lane == 0) { red[0][warp] = pS; red[1][warp] = pP; red[2][warp] = pN; }
    __syncthreads();
    if (t == 0) {
        out[g]            = red[0][0] + red[0][1] + hSb[0];
        out[NG + g]       = red[1][0] + red[1][1] + hPb[0];
        out[2 * NG + g]   = red[2][0] + red[2][1] + hNb[0];
    }
}

// ---------------------------------------------------------------------------
extern "C" void kernel_launch(void* const* d_in, const int* in_sizes, int n_in,
                              void* d_out, int out_size) {
    const float* x     = (const float*)d_in[0];
    const int*   ei    = (const int*)d_in[1];
    const float* eattr = (const float*)d_in[2];
    const int*   batch = (const int*)d_in[3];
    const float *e1w = (const float*)d_in[4],  *e1b = (const float*)d_in[5];
    const float *n1w1 = (const float*)d_in[6], *n1b1 = (const float*)d_in[7];
    const float *n1w2 = (const float*)d_in[8], *n1b2 = (const float*)d_in[9];
    const float *e2w = (const float*)d_in[10], *e2b = (const float*)d_in[11];
    const float *n2w1 = (const float*)d_in[12], *n2b1 = (const float*)d_in[13];
    const float *n2w2 = (const float*)d_in[14], *n2b2 = (const float*)d_in[15];
    const float *fcw = (const float*)d_in[16], *fcb = (const float*)d_in[17];
    const float *hSw = (const float*)d_in[18], *hSb = (const float*)d_in[19];
    const float *hPw = (const float*)d_in[20], *hPb = (const float*)d_in[21];
    const float *hNw = (const float*)d_in[22], *hNb = (const float*)d_in[23];
    float* out = (float*)d_out;

    void *pA, *pB, *pC, *pP;
    cudaGetSymbolAddress(&pA, g_bufA);
    cudaGetSymbolAddress(&pB, g_bufB);
    cudaGetSymbolAddress(&pC, g_bufC);
    cudaGetSymbolAddress(&pP, g_pool);
    float* A = (float*)pA; float* B = (float*)pB;
    float* C = (float*)pC; float* P = (float*)pP;

    const int n4 = NN * HID / 4;
    cudaFuncSetAttribute(edge_mma_kernel, cudaFuncAttributeMaxDynamicSharedMemorySize, SM_TOTAL_E);
    cudaFuncSetAttribute(gemm_mma_kernel, cudaFuncAttributeMaxDynamicSharedMemorySize, GM_TOTAL);
    const int gemm_blocks = (NN + 127) / 128;   // 391
    const int edge_blocks = 296;                // 2 persistent CTAs / SM

    // ----- Layer 1 -----
    copy_kernel<<<4096, 256>>>((const float4*)x, (float4*)A, n4);
    edge_mma_kernel<<<edge_blocks, 256, SM_TOTAL_E>>>(x, eattr, ei, e1w, e1b, A);
    gemm_mma_kernel<<<gemm_blocks, 256, GM_TOTAL>>>(A, n1w1, n1b1, B, NN, 1);
    gemm_mma_kernel<<<gemm_blocks, 256, GM_TOTAL>>>(B, n1w2, n1b2, C, NN, 1);

    // ----- Layer 2 -----
    copy_kernel<<<4096, 256>>>((const float4*)C, (float4*)A, n4);
    edge_mma_kernel<<<edge_blocks, 256, SM_TOTAL_E>>>(C, eattr, ei, e2w, e2b, A);
    gemm_mma_kernel<<<gemm_blocks, 256, GM_TOTAL>>>(A, n2w1, n2b1, B, NN, 1);
    gemm_mma_kernel<<<gemm_blocks, 256, GM_TOTAL>>>(B, n2w2, n2b2, C, NN, 1);

    // ----- Pool + heads -----
    pool_kernel<<<NG, HID>>>(C, batch, P);
    head_kernel<<<NG, 64>>>(P, fcw, fcb, hSw, hSb, hPw, hPb, hNw, hNb, out);
}

// round 14
// speedup vs baseline: 1.5914x; 1.0140x over previous
#include <cuda_runtime.h>
#include <cuda_bf16.h>
#include <cstdint>

#define NN 50000
#define NE 800000
#define NG 512
#define HID 128
#define EIN 64
#define NTILES (NE / 128)   // 6250 exactly

typedef unsigned long long ull;

// Scratch (device globals: allocation-free rule)
__device__ float g_bufA[NN * HID];   // aggr / MLP input
__device__ float g_bufB[NN * HID];   // MLP hidden
__device__ float g_bufC[NN * HID];   // layer output
__device__ float g_pool[NG * HID];   // pooled per-graph features

// ---- bf16 split helpers ----------------------------------------------------
__device__ __forceinline__ void split2(float a, float b, uint32_t& h, uint32_t& l) {
    __nv_bfloat16 ha = __float2bfloat16_rn(a), hb = __float2bfloat16_rn(b);
    __nv_bfloat162 hh; hh.x = ha; hh.y = hb;
    h = *(uint32_t*)&hh;
    __nv_bfloat162 ll;
    ll.x = __float2bfloat16_rn(a - __bfloat162float(ha));
    ll.y = __float2bfloat16_rn(b - __bfloat162float(hb));
    l = *(uint32_t*)&ll;
}
__device__ __forceinline__ uint32_t packhi2(float a, float b) {
    __nv_bfloat162 hh = __floats2bfloat162_rn(a, b);
    return *(uint32_t*)&hh;
}

__device__ __forceinline__ void mma_bf16(float& c0, float& c1, float& c2, float& c3,
                                         uint32_t a0, uint32_t a1, uint32_t a2, uint32_t a3,
                                         uint32_t b0, uint32_t b1) {
    asm volatile("mma.sync.aligned.m16n8k16.row.col.f32.bf16.bf16.f32 "
                 "{%0,%1,%2,%3}, {%4,%5,%6,%7}, {%8,%9}, {%0,%1,%2,%3};"
                 : "+f"(c0), "+f"(c1), "+f"(c2), "+f"(c3)
                 : "r"(a0), "r"(a1), "r"(a2), "r"(a3), "r"(b0), "r"(b1));
}

__device__ __forceinline__ void ldsm4(uint32_t& r0, uint32_t& r1, uint32_t& r2, uint32_t& r3,
                                      uint32_t addr) {
    asm volatile("ldmatrix.sync.aligned.m8n8.x4.shared.b16 {%0,%1,%2,%3}, [%4];"
                 : "=r"(r0), "=r"(r1), "=r"(r2), "=r"(r3) : "r"(addr));
}
__device__ __forceinline__ uint32_t smem_u32(const void* p) {
    return (uint32_t)__cvta_generic_to_shared(p);
}

// ---------------------------------------------------------------------------
__global__ void copy_kernel(const float4* __restrict__ s, float4* __restrict__ d, int n) {
    int i = blockIdx.x * blockDim.x + threadIdx.x;
    int stride = gridDim.x * blockDim.x;
    for (; i < n; i += stride) d[i] = s[i];
}

// ---------------------------------------------------------------------------
// Tensor-core edge kernel: aggr[dst] += relu(x[src] + attr @ W + b)
// attr in bf16 (hi only); W split hi/lo (2 MMA terms). 2 CTAs/SM, no spills.
#define KS 72
#define MSG_S 132
#define SM_WHI  0
#define SM_WLO  18432
#define SM_AHI  36864
#define SM_BIAS 55296
#define SM_MSG  55808      // 32*132*4 = 16896
#define SM_TOTAL_E 72704

__global__ void __launch_bounds__(256, 2)
edge_mma_kernel(const float* __restrict__ xin,
                const float* __restrict__ eattr,
                const int* __restrict__ ei,
                const float* __restrict__ W,       // [64,128]
                const float* __restrict__ bias,    // [128]
                float* __restrict__ aggr) {
    extern __shared__ char smem[];
    __nv_bfloat16* sWhi = (__nv_bfloat16*)(smem + SM_WHI);
    __nv_bfloat16* sWlo = (__nv_bfloat16*)(smem + SM_WLO);
    __nv_bfloat16* sAhi = (__nv_bfloat16*)(smem + SM_AHI);
    float* sBias = (float*)(smem + SM_BIAS);
    float* sMsg  = (float*)(smem + SM_MSG);

    int tid = threadIdx.x;
    int wid = tid >> 5, lane = tid & 31;
    int g = lane >> 2, q = lane & 3;
    int m0 = wid * 16;

    // Stage W transposed: sW[n*KS + k], hi/lo bf16
    {
        int n = tid >> 1, k0 = (tid & 1) * 32;
        for (int j = 0; j < 32; j++) {
            int k = k0 + j;
            float v = W[k * HID + n];
            __nv_bfloat16 h = __float2bfloat16_rn(v);
            sWhi[n * KS + k] = h;
            sWlo[n * KS + k] = __float2bfloat16_rn(v - __bfloat162float(h));
        }
    }
    if (tid < HID) sBias[tid] = bias[tid];
    __syncthreads();

    // ldmatrix per-lane addresses
    int a_row = m0 + (lane & 7) + ((lane >> 3) & 1) * 8;
    int a_k   = (lane >> 4) * 8;
    uint32_t aHoff = smem_u32(sAhi) + (uint32_t)(a_row * KS + a_k) * 2;
    int b_n = (lane & 7) + ((lane >> 4) & 1) * 8;
    int b_k = ((lane >> 3) & 1) * 8;
    uint32_t bHoff = smem_u32(sWhi) + (uint32_t)(b_n * KS + b_k) * 2;
    uint32_t bLoff = smem_u32(sWlo) + (uint32_t)(b_n * KS + b_k) * 2;

    const int* src = ei;
    const int* dst = ei + NE;
    int srow = tid >> 3;
    int sgrp = tid & 7;

    for (int tile = blockIdx.x; tile < NTILES; tile += gridDim.x) {
        int ebase = tile * 128;
        // stage attr tile: sA[r*KS + k], bf16 hi only
        {
            int r = tid >> 1, k0 = (tid & 1) * 32;
            const float4* ap = (const float4*)(eattr + (size_t)(ebase + r) * EIN + k0);
            #pragma unroll
            for (int j = 0; j < 8; j++) {
                float4 v = ap[j];
                *(uint2*)&sAhi[r * KS + k0 + j * 4] =
                    make_uint2(packhi2(v.x, v.y), packhi2(v.z, v.w));
            }
        }
        __syncthreads();

        float acc[16][4];
        #pragma unroll
        for (int nt = 0; nt < 16; nt++)
            #pragma unroll
            for (int c = 0; c < 4; c++) acc[nt][c] = 0.f;

        #pragma unroll
        for (int kt = 0; kt < 4; kt++) {
            uint32_t aH0, aH1, aH2, aH3;
            ldsm4(aH0, aH1, aH2, aH3, aHoff + kt * 32);
            #pragma unroll
            for (int np = 0; np < 8; np++) {
                uint32_t e0, e1, o0, o1;
                uint32_t bofs = np * (16 * KS * 2) + kt * 32;
                ldsm4(e0, e1, o0, o1, bHoff + bofs);
                int nte = np * 2, nto = np * 2 + 1;
                mma_bf16(acc[nte][0], acc[nte][1], acc[nte][2], acc[nte][3],
                         aH0, aH1, aH2, aH3, e0, e1);
                mma_bf16(acc[nto][0], acc[nto][1], acc[nto][2], acc[nto][3],
                         aH0, aH1, aH2, aH3, o0, o1);
                ldsm4(e0, e1, o0, o1, bLoff + bofs);
                mma_bf16(acc[nte][0], acc[nte][1], acc[nte][2], acc[nte][3],
                         aH0, aH1, aH2, aH3, e0, e1);
                mma_bf16(acc[nto][0], acc[nto][1], acc[nto][2], acc[nto][3],
                         aH0, aH1, aH2, aH3, o0, o1);
            }
        }

        // Epilogue: 4 chunks of 32 rows through sMsg, then float4 gather+RED.128
        #pragma unroll
        for (int c = 0; c < 4; c++) {
            if ((wid >> 1) == c) {
                int h = wid & 1;
                #pragma unroll
                for (int nt = 0; nt < 16; nt++) {
                    int col = nt * 8 + 2 * q;
                    *(float2*)&sMsg[(h * 16 + g) * MSG_S + col] =
                        make_float2(acc[nt][0], acc[nt][1]);
                    *(float2*)&sMsg[(h * 16 + g + 8) * MSG_S + col] =
                        make_float2(acc[nt][2], acc[nt][3]);
                }
            }
            __syncthreads();
            int eid = ebase + c * 32 + srow;
            int sI = src[eid], dI = dst[eid];
            const float* xr = xin + (size_t)sI * HID;
            float* ar = aggr + (size_t)dI * HID;
            #pragma unroll
            for (int j = 0; j < 4; j++) {
                int col = (sgrp + j * 8) * 4;
                float4 mv = *(const float4*)&sMsg[srow * MSG_S + col];
                float4 xv = *(const float4*)(xr + col);
                float4 bb = *(const float4*)(sBias + col);
                float4 m;
                m.x = fmaxf(xv.x + bb.x + mv.x, 0.f);
                m.y = fmaxf(xv.y + bb.y + mv.y, 0.f);
                m.z = fmaxf(xv.z + bb.z + mv.z, 0.f);
                m.w = fmaxf(xv.w + bb.w + mv.w, 0.f);
                atomicAdd((float4*)(ar + col), m);
            }
            __syncthreads();
        }
    }
}

// ---------------------------------------------------------------------------
// Tensor-core node GEMM: C[M,128] = act(A[M,128] @ W[128,128] + bias)
// 192-row x 128-col tile, K=128 (2 chunks of 64), 384 threads (12 warps).
// Single wave: 261 blocks <= 296 resident slots. Optional dual output C2.
#define GKS 136
#define GM_WHI  0            // 128*136*2 = 34816
#define GM_WLO  34816
#define GM_AHI  69632        // 192*72*2 = 27648
#define GM_ALO  97280        // 27648
#define GM_BIAS 124928
#define GM_TOTAL 125440

__global__ void __launch_bounds__(384, 1)
gemm_mma_kernel(const float* __restrict__ A,
                const float* __restrict__ W,       // [128,128]
                const float* __restrict__ bias,
                float* __restrict__ C,
                float* __restrict__ C2,            // optional dual store
                int M, int doRelu) {
    extern __shared__ char smem[];
    __nv_bfloat16* sWhi = (__nv_bfloat16*)(smem + GM_WHI);
    __nv_bfloat16* sWlo = (__nv_bfloat16*)(smem + GM_WLO);
    __nv_bfloat16* sAhi = (__nv_bfloat16*)(smem + GM_AHI);
    __nv_bfloat16* sAlo = (__nv_bfloat16*)(smem + GM_ALO);
    float* sBias = (float*)(smem + GM_BIAS);

    int tid = threadIdx.x;
    int wid = tid >> 5, lane = tid & 31;
    int g = lane >> 2, q = lane & 3;
    int m0 = wid * 16;
    int brow = blockIdx.x * 192;

    // Stage W transposed: sW[n*GKS + k], k=0..127, hi/lo (first 256 threads)
    if (tid < 256) {
        int n = tid >> 1, k0 = (tid & 1) * 64;
        for (int j = 0; j < 64; j++) {
            int k = k0 + j;
            float v = W[k * HID + n];
            __nv_bfloat16 h = __float2bfloat16_rn(v);
            sWhi[n * GKS + k] = h;
            sWlo[n * GKS + k] = __float2bfloat16_rn(v - __bfloat162float(h));
        }
    }
    if (tid < HID) sBias[tid] = bias[tid];

    int a_row = m0 + (lane & 7) + ((lane >> 3) & 1) * 8;
    int a_k   = (lane >> 4) * 8;
    uint32_t aHoff = smem_u32(sAhi) + (uint32_t)(a_row * KS + a_k) * 2;
    uint32_t aLoff = smem_u32(sAlo) + (uint32_t)(a_row * KS + a_k) * 2;
    int b_n = (lane & 7) + ((lane >> 4) & 1) * 8;
    int b_k = ((lane >> 3) & 1) * 8;
    uint32_t bHoff = smem_u32(sWhi) + (uint32_t)(b_n * GKS + b_k) * 2;
    uint32_t bLoff = smem_u32(sWlo) + (uint32_t)(b_n * GKS + b_k) * 2;

    float acc[16][4];
    #pragma unroll
    for (int nt = 0; nt < 16; nt++)
        #pragma unroll
        for (int c = 0; c < 4; c++) acc[nt][c] = 0.f;

    for (int chunk = 0; chunk < 2; chunk++) {
        // stage A chunk: rows brow..+191 (2 threads/row), k = chunk*64..+63
        {
            int r = tid >> 1, k0 = (tid & 1) * 32;
            int grow = brow + r;
            float4 z = make_float4(0.f, 0.f, 0.f, 0.f);
            const float4* ap = (const float4*)(A + (size_t)grow * HID + chunk * 64 + k0);
            #pragma unroll
            for (int j = 0; j < 8; j++) {
                float4 v = (grow < M) ? ap[j] : z;
                uint32_t h0, l0, h1, l1;
                split2(v.x, v.y, h0, l0);
                split2(v.z, v.w, h1, l1);
                *(uint2*)&sAhi[r * KS + k0 + j * 4] = make_uint2(h0, h1);
                *(uint2*)&sAlo[r * KS + k0 + j * 4] = make_uint2(l0, l1);
            }
        }
        __syncthreads();

        #pragma unroll
        for (int kt = 0; kt < 4; kt++) {
            uint32_t aH0, aH1, aH2, aH3, aL0, aL1, aL2, aL3;
            ldsm4(aH0, aH1, aH2, aH3, aHoff + kt * 32);
            ldsm4(aL0, aL1, aL2, aL3, aLoff + kt * 32);
            uint32_t kofs = (uint32_t)(chunk * 64 + kt * 16) * 2;
            #pragma unroll
            for (int np = 0; np < 8; np++) {
                uint32_t e0, e1, o0, o1;
                uint32_t bofs = np * (16 * GKS * 2) + kofs;
                ldsm4(e0, e1, o0, o1, bHoff + bofs);
                int nte = np * 2, nto = np * 2 + 1;
                mma_bf16(acc[nte][0], acc[nte][1], acc[nte][2], acc[nte][3],
                         aH0, aH1, aH2, aH3, e0, e1);
                mma_bf16(acc[nto][0], acc[nto][1], acc[nto][2], acc[nto][3],
                         aH0, aH1, aH2, aH3, o0, o1);
                mma_bf16(acc[nte][0], acc[nte][1], acc[nte][2], acc[nte][3],
                         aL0, aL1, aL2, aL3, e0, e1);
                mma_bf16(acc[nto][0], acc[nto][1], acc[nto][2], acc[nto][3],
                         aL0, aL1, aL2, aL3, o0, o1);
                ldsm4(e0, e1, o0, o1, bLoff + bofs);
                mma_bf16(acc[nte][0], acc[nte][1], acc[nte][2], acc[nte][3],
                         aH0, aH1, aH2, aH3, e0, e1);
                mma_bf16(acc[nto][0], acc[nto][1], acc[nto][2], acc[nto][3],
                         aH0, aH1, aH2, aH3, o0, o1);
            }
        }
        __syncthreads();
    }

    // Epilogue: rows brow+m0+g (+8), cols nt*8+2q
    int r0 = brow + m0 + g;
    int r1 = r0 + 8;
    bool dual = (C2 != nullptr);
    #pragma unroll
    for (int nt = 0; nt < 16; nt++) {
        int col = nt * 8 + 2 * q;
        float2 bb = *(const float2*)(sBias + col);
        if (r0 < M) {
            float ox = acc[nt][0] + bb.x, oy = acc[nt][1] + bb.y;
            if (doRelu) { ox = fmaxf(ox, 0.f); oy = fmaxf(oy, 0.f); }
            float2 o = make_float2(ox, oy);
            *(float2*)&C[(size_t)r0 * HID + col] = o;
            if (dual) *(float2*)&C2[(size_t)r0 * HID + col] = o;
        }
        if (r1 < M) {
            float ox = acc[nt][2] + bb.x, oy = acc[nt][3] + bb.y;
            if (doRelu) { ox = fmaxf(ox, 0.f); oy = fmaxf(oy, 0.f); }
            float2 o = make_float2(ox, oy);
            *(float2*)&C[(size_t)r1 * HID + col] = o;
            if (dual) *(float2*)&C2[(size_t)r1 * HID + col] = o;
        }
    }
}

// ---------------------------------------------------------------------------
__global__ void pool_kernel(const float* __restrict__ h,
                            const int* __restrict__ batch,
                            float* __restrict__ pool) {
    __shared__ int bounds[2];
    int g = blockIdx.x, t = threadIdx.x;  // 128 threads
    if (t < 2) {
        int target = g + t;
        int lo = 0, hi = NN;
        while (lo < hi) {
            int mid = (lo + hi) >> 1;
            if (batch[mid] < target) lo = mid + 1; else hi = mid;
        }
        bounds[t] = lo;
    }
    __syncthreads();
    int lo = bounds[0], hi = bounds[1];
    float s = 0.f;
    for (int n = lo; n < hi; n++) s += h[(size_t)n * HID + t];
    float cnt = (float)((hi - lo) > 1 ? (hi - lo) : 1);
    pool[g * HID + t] = s / cnt;
}

// ---------------------------------------------------------------------------
__global__ void head_kernel(const float* __restrict__ pool,
                            const float* __restrict__ fcw, const float* __restrict__ fcb,
                            const float* __restrict__ hSw, const float* __restrict__ hSb,
                            const float* __restrict__ hPw, const float* __restrict__ hPb,
                            const float* __restrict__ hNw, const float* __restrict__ hNb,
                            float* __restrict__ out) {
    __shared__ float sg[HID];
    __shared__ float red[3][2];
    int g = blockIdx.x, t = threadIdx.x;  // 64 threads
    sg[t]      = pool[g * HID + t];
    sg[t + 64] = pool[g * HID + t + 64];
    __syncthreads();
    float a = fcb[t];
    #pragma unroll 4
    for (int k = 0; k < HID; k++) a = fmaf(sg[k], fcw[k * 64 + t], a);
    float s = fmaxf(a, 0.f);
    float pS = s * hSw[t], pP = s * hPw[t], pN = s * hNw[t];
    #pragma unroll
    for (int off = 16; off; off >>= 1) {
        pS += __shfl_down_sync(0xffffffffu, pS, off);
        pP += __shfl_down_sync(0xffffffffu, pP, off);
        pN += __shfl_down_sync(0xffffffffu, pN, off);
    }
    int warp = t >> 5, lane = t & 31;
    if (lane == 0) { red[0][warp] = pS; red[1][warp] = pP; red[2][warp] = pN; }
    __syncthreads();
    if (t == 0) {
        out[g]            = red[0][0] + red[0][1] + hSb[0];
        out[NG + g]       = red[1][0] + red[1][1] + hPb[0];
        out[2 * NG + g]   = red[2][0] + red[2][1] + hNb[0];
    }
}

// ---------------------------------------------------------------------------
extern "C" void kernel_launch(void* const* d_in, const int* in_sizes, int n_in,
                              void* d_out, int out_size) {
    const float* x     = (const float*)d_in[0];
    const int*   ei    = (const int*)d_in[1];
    const float* eattr = (const float*)d_in[2];
    const int*   batch = (const int*)d_in[3];
    const float *e1w = (const float*)d_in[4],  *e1b = (const float*)d_in[5];
    const float *n1w1 = (const float*)d_in[6], *n1b1 = (const float*)d_in[7];
    const float *n1w2 = (const float*)d_in[8], *n1b2 = (const float*)d_in[9];
    const float *e2w = (const float*)d_in[10], *e2b = (const float*)d_in[11];
    const float *n2w1 = (const float*)d_in[12], *n2b1 = (const float*)d_in[13];
    const float *n2w2 = (const float*)d_in[14], *n2b2 = (const float*)d_in[15];
    const float *fcw = (const float*)d_in[16], *fcb = (const float*)d_in[17];
    const float *hSw = (const float*)d_in[18], *hSb = (const float*)d_in[19];
    const float *hPw = (const float*)d_in[20], *hPb = (const float*)d_in[21];
    const float *hNw = (const float*)d_in[22], *hNb = (const float*)d_in[23];
    float* out = (float*)d_out;

    void *pA, *pB, *pC, *pP;
    cudaGetSymbolAddress(&pA, g_bufA);
    cudaGetSymbolAddress(&pB, g_bufB);
    cudaGetSymbolAddress(&pC, g_bufC);
    cudaGetSymbolAddress(&pP, g_pool);
    float* A = (float*)pA; float* B = (float*)pB;
    float* C = (float*)pC; float* P = (float*)pP;

    const int n4 = NN * HID / 4;
    cudaFuncSetAttribute(edge_mma_kernel, cudaFuncAttributeMaxDynamicSharedMemorySize, SM_TOTAL_E);
    cudaFuncSetAttribute(gemm_mma_kernel, cudaFuncAttributeMaxDynamicSharedMemorySize, GM_TOTAL);
    const int gemm_blocks = (NN + 191) / 192;   // 261 -> single wave
    const int edge_blocks = 296;                // 2 persistent CTAs / SM

    // ----- Layer 1 -----
    copy_kernel<<<4096, 256>>>((const float4*)x, (float4*)A, n4);
    edge_mma_kernel<<<edge_blocks, 256, SM_TOTAL_E>>>(x, eattr, ei, e1w, e1b, A);
    gemm_mma_kernel<<<gemm_blocks, 384, GM_TOTAL>>>(A, n1w1, n1b1, B, nullptr, NN, 1);
    gemm_mma_kernel<<<gemm_blocks, 384, GM_TOTAL>>>(B, n1w2, n1b2, C, A, NN, 1);  // dual: C + aggr-init

    // ----- Layer 2 -----
    edge_mma_kernel<<<edge_blocks, 256, SM_TOTAL_E>>>(C, eattr, ei, e2w, e2b, A);
    gemm_mma_kernel<<<gemm_blocks, 384, GM_TOTAL>>>(A, n2w1, n2b1, B, nullptr, NN, 1);
    gemm_mma_kernel<<<gemm_blocks, 384, GM_TOTAL>>>(B, n2w2, n2b2, C, nullptr, NN, 1);

    // ----- Pool + heads -----
    pool_kernel<<<NG, HID>>>(C, batch, P);
    head_kernel<<<NG, 64>>>(P, fcw, fcb, hSw, hSb, hPw, hPb, hNw, hNb, out);
}